// round 12
// baseline (speedup 1.0000x reference)
#include <cuda_runtime.h>
#include <cuda_fp16.h>
#include <math.h>
#include <stdint.h>

#define B 64
#define S 300
#define DM 1024
#define P 128
#define H 4
#define C 3862
#define BSZ (B*S)        /* 19200 */
#define NQ 768           /* 128 key + 128 val + 4*128 q */

// ---------------- scratch (static device globals; no allocation) ----------------
__device__ __align__(16) __half g_Ahi[(size_t)BSZ * DM];
__device__ __align__(16) __half g_Alo[(size_t)BSZ * DM];
__device__ __align__(16) __half g_Whi[NQ * DM];
__device__ __align__(16) __half g_Wlo[NQ * DM];
__device__ float g_bf[NQ];                 // fused bias
__device__ float g_qkv[(size_t)BSZ * NQ];  // [19200,768] fp32
__device__ float g_ws[B * H * P];
__device__ float g_logits[B * H * C];
__device__ float g_rowsum[C];

// ================= helpers =================
__device__ __forceinline__ uint32_t smem_u32(const void* p) {
    uint32_t a;
    asm("{ .reg .u64 t; cvta.to.shared.u64 t, %1; cvt.u32.u64 %0, t; }" : "=r"(a) : "l"(p));
    return a;
}
__device__ __forceinline__ void cp16(uint32_t s, const void* gp) {
    asm volatile("cp.async.cg.shared.global [%0], [%1], 16;" :: "r"(s), "l"(gp) : "memory");
}
__device__ __forceinline__ void ldsm4(uint32_t* r, uint32_t addr) {
    asm volatile("ldmatrix.sync.aligned.m8n8.x4.shared.b16 {%0,%1,%2,%3}, [%4];"
                 : "=r"(r[0]), "=r"(r[1]), "=r"(r[2]), "=r"(r[3]) : "r"(addr));
}
__device__ __forceinline__ void mma16816(float* c, const uint32_t* a, const uint32_t* b) {
    asm volatile("mma.sync.aligned.m16n8k16.row.col.f32.f16.f16.f32 "
                 "{%0,%1,%2,%3}, {%4,%5,%6,%7}, {%8,%9}, {%0,%1,%2,%3};"
                 : "+f"(c[0]), "+f"(c[1]), "+f"(c[2]), "+f"(c[3])
                 : "r"(a[0]), "r"(a[1]), "r"(a[2]), "r"(a[3]), "r"(b[0]), "r"(b[1]));
}

// ---------------- K0a: convert seg_features to split fp16 ----------------
__global__ void conv_seg(const float4* __restrict__ in, int n4) {
    int i = blockIdx.x * blockDim.x + threadIdx.x;
    if (i >= n4) return;
    float4 v = in[i];
    __half h0 = __float2half(v.x), h1 = __float2half(v.y);
    __half h2 = __float2half(v.z), h3 = __float2half(v.w);
    __half l0 = __float2half(v.x - __half2float(h0));
    __half l1 = __float2half(v.y - __half2float(h1));
    __half l2 = __float2half(v.z - __half2float(h2));
    __half l3 = __float2half(v.w - __half2float(h3));
    uint2 hw, lw;
    hw.x = (uint32_t)__half_as_ushort(h0) | ((uint32_t)__half_as_ushort(h1) << 16);
    hw.y = (uint32_t)__half_as_ushort(h2) | ((uint32_t)__half_as_ushort(h3) << 16);
    lw.x = (uint32_t)__half_as_ushort(l0) | ((uint32_t)__half_as_ushort(l1) << 16);
    lw.y = (uint32_t)__half_as_ushort(l2) | ((uint32_t)__half_as_ushort(l3) << 16);
    ((uint2*)g_Ahi)[i] = hw;
    ((uint2*)g_Alo)[i] = lw;
}

// ---------------- K0b: fuse+convert weights (blocks 0..3071) + Wc rowsums (blocks 3072+) ----------------
__global__ void fuse_wr(const float* __restrict__ Wq, const float* __restrict__ bq,
                        const float* __restrict__ Wk, const float* __restrict__ bk,
                        const float* __restrict__ Wv, const float* __restrict__ bv,
                        const float* __restrict__ Wc) {
    int blk = blockIdx.x;
    if (blk < 3072) {
        int idx = blk * 256 + threadIdx.x;
        if (idx < NQ * DM) {
            int n = idx >> 10, k = idx & 1023;
            float v;
            if (n < 128)      v = Wk[n * DM + k];
            else if (n < 256) v = Wv[(n - 128) * DM + k];
            else              v = Wq[(n - 256) * DM + k];
            __half h = __float2half(v);
            g_Whi[idx] = h;
            g_Wlo[idx] = __float2half(v - __half2float(h));
        }
        if (idx < NQ) {
            float v;
            if (idx < 128)      v = bk[idx];
            else if (idx < 256) v = bv[idx - 128];
            else                v = bq[idx - 256];
            g_bf[idx] = v;
        }
    } else {
        int w = ((blk - 3072) * 256 + threadIdx.x) >> 5;
        int lane = threadIdx.x & 31;
        if (w >= C) return;
        float4 v = *(const float4*)(Wc + (size_t)w * P + lane * 4);
        float s_ = v.x + v.y + v.z + v.w;
#pragma unroll
        for (int o = 16; o; o >>= 1) s_ += __shfl_xor_sync(0xffffffffu, s_, o);
        if (lane == 0) g_rowsum[w] = s_;
    }
}

// ---------------- K1: HMMA 3-term fp16 GEMM (R11 config, measured best) ----------------
#define STG_A_LO  6144u
#define STG_B_HI 12288u
#define STG_B_LO 18432u
#define STG_BYTES 24576u
#define GEMM_SMEM (4u * STG_BYTES)

__device__ __forceinline__ void load_stage(uint32_t sstage, int bm, int bn, int k0, int tid) {
#pragma unroll
    for (int i = 0; i < 8; i++) {
        int id = tid + i * 128;
        int sel = id >> 8;
        int j = id & 255;
        int row = j >> 1, kc = j & 1;
        uint32_t toff = (sel == 0) ? 0u : (sel == 1) ? STG_A_LO : (sel == 2) ? STG_B_HI : STG_B_LO;
        const __half* g = (sel == 0) ? g_Ahi : (sel == 1) ? g_Alo : (sel == 2) ? g_Whi : g_Wlo;
        int grow = (sel < 2) ? (bm + row) : (bn + row);
        cp16(sstage + toff + (uint32_t)(row * 48 + kc * 16),
             g + (size_t)grow * DM + k0 + kc * 8);
    }
    asm volatile("cp.async.commit_group;" ::: "memory");
}

__global__ __launch_bounds__(128, 2) void gemm_mma() {
    extern __shared__ char sm_[];
    uint32_t sbase = smem_u32(sm_);
    const int tid = threadIdx.x;
    const int wid = tid >> 5, lane = tid & 31;
    const int bm = blockIdx.y * 128, bn = blockIdx.x * 128;
    const int wm = (wid >> 1) * 64;
    const int wn = (wid & 1) * 64;
    const int g = lane >> 2, t = lane & 3;

    const uint32_t a_row = (uint32_t)(wm + (lane & 7) + ((lane >> 3) & 1) * 8);
    const uint32_t a_col = (uint32_t)((lane >> 4) * 16);
    const uint32_t b_row = (uint32_t)(wn + (lane & 7) + ((lane >> 4) & 1) * 8);
    const uint32_t b_col = (uint32_t)(((lane >> 3) & 1) * 16);

    float acc[4][8][4];
#pragma unroll
    for (int a = 0; a < 4; a++)
#pragma unroll
        for (int b = 0; b < 8; b++)
#pragma unroll
            for (int c = 0; c < 4; c++) acc[a][b][c] = 0.f;

    load_stage(sbase,                 bm, bn,  0, tid);
    load_stage(sbase + STG_BYTES,     bm, bn, 16, tid);
    load_stage(sbase + 2 * STG_BYTES, bm, bn, 32, tid);

    for (int kt = 0; kt < 64; kt++) {
        asm volatile("cp.async.wait_group 2;" ::: "memory");
        __syncthreads();
        if (kt + 3 < 64)
            load_stage(sbase + (uint32_t)((kt + 3) & 3) * STG_BYTES, bm, bn, (kt + 3) * 16, tid);
        else
            asm volatile("cp.async.commit_group;" ::: "memory");

        uint32_t st = sbase + (uint32_t)(kt & 3) * STG_BYTES;
        uint32_t ah[4][4], al[4][4];
#pragma unroll
        for (int mt = 0; mt < 4; mt++) {
            uint32_t ad = st + (a_row + (uint32_t)(mt * 16)) * 48u + a_col;
            ldsm4(ah[mt], ad);
            ldsm4(al[mt], ad + STG_A_LO);
        }
        uint32_t bh[2][4], bl[2][4];
        {
            uint32_t bd = st + STG_B_HI + b_row * 48u + b_col;
            ldsm4(bh[0], bd);
            ldsm4(bl[0], bd + (STG_B_LO - STG_B_HI));
        }
#pragma unroll
        for (int p = 0; p < 4; p++) {
            int cur = p & 1;
            if (p < 3) {
                uint32_t bd = st + STG_B_HI + (b_row + (uint32_t)((p + 1) * 16)) * 48u + b_col;
                ldsm4(bh[cur ^ 1], bd);
                ldsm4(bl[cur ^ 1], bd + (STG_B_LO - STG_B_HI));
            }
#pragma unroll
            for (int term = 0; term < 3; term++) {
#pragma unroll
                for (int sub = 0; sub < 2; sub++) {
#pragma unroll
                    for (int mt = 0; mt < 4; mt++) {
                        const uint32_t* af = (term == 2) ? al[mt] : ah[mt];
                        const uint32_t* bf = (term == 1) ? &bl[cur][2 * sub] : &bh[cur][2 * sub];
                        mma16816(acc[mt][p * 2 + sub], af, bf);
                    }
                }
            }
        }
    }

#pragma unroll
    for (int mt = 0; mt < 4; mt++) {
        int r0 = bm + wm + mt * 16 + g;
#pragma unroll
        for (int nt = 0; nt < 8; nt++) {
            int col = bn + wn + nt * 8 + 2 * t;
            float2 bv = *(const float2*)(g_bf + col);
            float2 v0 = { acc[mt][nt][0] + bv.x, acc[mt][nt][1] + bv.y };
            *(float2*)(g_qkv + (size_t)r0 * NQ + col) = v0;
            float2 v1 = { acc[mt][nt][2] + bv.x, acc[mt][nt][3] + bv.y };
            *(float2*)(g_qkv + (size_t)(r0 + 8) * NQ + col) = v1;
        }
    }
}

// ---------------- K2: fused scores + softmax + ws, one block per batch ----------------
__global__ __launch_bounds__(512) void attn_k(float* __restrict__ sco_out,
                                              float* __restrict__ attw_out) {
    int b = blockIdx.x;
    int tid = threadIdx.x, w = tid >> 5, l = tid & 31;
    __shared__ float sc[4][304];
    __shared__ float red[512];

    // phase 1: scores[h][s] = dot(q_hs, k_s) * scale   (K row loaded once for 4 heads)
    for (int s = w; s < S; s += 16) {
        const float* row = g_qkv + (size_t)(b * S + s) * NQ;
        float4 k4 = *(const float4*)(row + l * 4);
#pragma unroll
        for (int h = 0; h < 4; h++) {
            float4 q4 = *(const float4*)(row + 256 + h * 128 + l * 4);
            float d = q4.x * k4.x + q4.y * k4.y + q4.z * k4.z + q4.w * k4.w;
#pragma unroll
            for (int o = 16; o; o >>= 1) d += __shfl_xor_sync(0xffffffffu, d, o);
            if (l == 0) {
                float v = d * 0.08838834764831845f;
                sc[h][s] = v;
                sco_out[(size_t)(b * S + s) * H + h] = v;
            }
        }
    }
    __syncthreads();

    // phase 2: softmax per head (4 groups of 128 threads)
    int hg = tid >> 7, ti = tid & 127;
    float m = -1e30f;
    for (int s = ti; s < S; s += 128) m = fmaxf(m, sc[hg][s]);
    red[tid] = m; __syncthreads();
    for (int o = 64; o; o >>= 1) { if (ti < o) red[tid] = fmaxf(red[tid], red[tid + o]); __syncthreads(); }
    float mx = red[hg * 128]; __syncthreads();
    float e[3]; int cnt = 0; float esum = 0.f;
    for (int s = ti; s < S; s += 128) { float ev = expf(sc[hg][s] - mx); e[cnt++] = ev; esum += ev; }
    red[tid] = esum; __syncthreads();
    for (int o = 64; o; o >>= 1) { if (ti < o) red[tid] += red[tid + o]; __syncthreads(); }
    float inv = 1.f / red[hg * 128];
    __syncthreads();
    cnt = 0;
    for (int s = ti; s < S; s += 128) {
        float pr = e[cnt++] * inv;
        sc[hg][s] = pr;
        attw_out[(size_t)(b * S + s) * H + hg] = pr;
    }
    __syncthreads();

    // phase 3: ws[h][p] = relu(sum_s prob * V[s][p])   (V resident in L1 across groups)
    int p = tid & 127, h = tid >> 7;
    const float* vp = g_qkv + (size_t)b * S * NQ + 128 + p;
    float a0 = 0.f, a1 = 0.f;
#pragma unroll 2
    for (int s = 0; s < 300; s += 2) {
        a0 = fmaf(sc[h][s],     vp[(size_t)s * NQ], a0);
        a1 = fmaf(sc[h][s + 1], vp[(size_t)(s + 1) * NQ], a1);
    }
    g_ws[(b * H + h) * P + p] = fmaxf(a0 + a1, 0.f);
}

// ---------------- K5a: logits = relu(ws) @ Wc^T + bc  (register-tiled SIMT GEMM) ----------------
#define LG_CW 68
#define LG_RW 136
__global__ __launch_bounds__(256) void logits_gemm2(const float* __restrict__ Wc,
                                                    const float* __restrict__ bc) {
    __shared__ float sWcT[128][LG_CW];
    __shared__ float sWsT[128][LG_RW];
    int tid = threadIdx.x;
    int c_base = blockIdx.x * 64, r_base = blockIdx.y * 128;

#pragma unroll
    for (int u = 0; u < 8; u++) {
        int idx = tid + u * 256;
        int c = idx >> 5, kq = idx & 31;
        float4 v = make_float4(0.f, 0.f, 0.f, 0.f);
        if (c_base + c < C) v = *(const float4*)(Wc + (size_t)(c_base + c) * P + kq * 4);
        sWcT[kq * 4 + 0][c] = v.x; sWcT[kq * 4 + 1][c] = v.y;
        sWcT[kq * 4 + 2][c] = v.z; sWcT[kq * 4 + 3][c] = v.w;
    }
#pragma unroll
    for (int u = 0; u < 16; u++) {
        int idx = tid + u * 256;
        int r = idx >> 5, kq = idx & 31;
        float4 v = *(const float4*)(g_ws + (size_t)(r_base + r) * P + kq * 4);
        sWsT[kq * 4 + 0][r] = v.x; sWsT[kq * 4 + 1][r] = v.y;
        sWsT[kq * 4 + 2][r] = v.z; sWsT[kq * 4 + 3][r] = v.w;
    }
    __syncthreads();

    int cg = tid & 15, rg = tid >> 4;
    float acc[4][8];
#pragma unroll
    for (int i = 0; i < 4; i++)
#pragma unroll
        for (int j = 0; j < 8; j++) acc[i][j] = 0.f;

    for (int k = 0; k < 128; k++) {
        float4 a4 = *(const float4*)&sWcT[k][cg * 4];
        float4 b0 = *(const float4*)&sWsT[k][rg * 8];
        float4 b1 = *(const float4*)&sWsT[k][rg * 8 + 4];
        float a[4] = { a4.x, a4.y, a4.z, a4.w };
        float bb[8] = { b0.x, b0.y, b0.z, b0.w, b1.x, b1.y, b1.z, b1.w };
#pragma unroll
        for (int i = 0; i < 4; i++)
#pragma unroll
            for (int j = 0; j < 8; j++)
                acc[i][j] = fmaf(a[i], bb[j], acc[i][j]);
    }

#pragma unroll
    for (int i = 0; i < 4; i++) {
        int c = c_base + cg * 4 + i;
        if (c >= C) continue;
        float bcv = bc[c];
#pragma unroll
        for (int j = 0; j < 8; j++) {
            int r = r_base + rg * 8 + j;
            g_logits[(size_t)r * C + c] = acc[i][j] + bcv;
        }
    }
}

// ---------------- K5b: LayerNorm (torch variant) in-place on g_logits ----------------
__global__ __launch_bounds__(512) void ln_k(const float* __restrict__ lna,
                                            const float* __restrict__ lnb) {
    int row = blockIdx.x;
    __shared__ float slog[C];
    __shared__ float red[512];
    int t = threadIdx.x;
    for (int c = t; c < C; c += 512) slog[c] = g_logits[(size_t)row * C + c];
    __syncthreads();
    float ps = 0.f;
    for (int c = t; c < C; c += 512) ps += slog[c];
    red[t] = ps; __syncthreads();
    for (int o = 256; o; o >>= 1) { if (t < o) red[t] += red[t + o]; __syncthreads(); }
    float mean = red[0] / C; __syncthreads();
    float ps2 = 0.f;
    for (int c = t; c < C; c += 512) { float dd = slog[c] - mean; ps2 += dd * dd; }
    red[t] = ps2; __syncthreads();
    for (int o = 256; o; o >>= 1) { if (t < o) red[t] += red[t + o]; __syncthreads(); }
    float stdv = sqrtf(red[0] / (C - 1));
    float inv = 1.f / (stdv + 1e-6f);
    for (int c = t; c < C; c += 512)
        g_logits[(size_t)row * C + c] = lna[c] * (slog[c] - mean) * inv + lnb[c];
}

// ---------------- K6: per (b,c) max/argmax over H, sigmoid ----------------
__global__ void final_k(float* __restrict__ vid, float* __restrict__ idc) {
    int idx = blockIdx.x * blockDim.x + threadIdx.x;
    if (idx >= B * C) return;
    int b = idx / C, c = idx % C;
    const float* lp = g_logits + (size_t)b * H * C + c;
    float best = lp[0]; int arg = 0;
#pragma unroll
    for (int h = 1; h < H; h++) {
        float v = lp[(size_t)h * C];
        if (v > best) { best = v; arg = h; }
    }
    vid[idx] = 1.f / (1.f + expf(-best));
    idc[idx] = (float)arg;
}

// ---------------- K7: conv regularizer finisher (1 block, cheap) ----------------
__global__ __launch_bounds__(1024) void convfin_k(const float* __restrict__ bc,
                                                  float* __restrict__ out) {
    __shared__ float red[1024];
    int t = threadIdx.x;
    float v[4]; float lm = -1e30f;
#pragma unroll
    for (int j = 0; j < 4; j++) {
        int c = t + j * 1024;
        if (c < C) { v[j] = g_rowsum[c] + bc[c]; lm = fmaxf(lm, v[j]); }
        else v[j] = -1e30f;
    }
    red[t] = lm; __syncthreads();
    for (int o = 512; o; o >>= 1) { if (t < o) red[t] = fmaxf(red[t], red[t + o]); __syncthreads(); }
    float mx = red[0]; __syncthreads();
    float e[4]; float psum = 0.f;
#pragma unroll
    for (int j = 0; j < 4; j++) {
        int c = t + j * 1024;
        e[j] = (c < C) ? expf(v[j] - mx) : 0.f;
        psum += e[j];
    }
    red[t] = psum; __syncthreads();
    for (int o = 512; o; o >>= 1) { if (t < o) red[t] += red[t + o]; __syncthreads(); }
    float invt = 1.f / red[0]; __syncthreads();
    float sp = 0.f;
#pragma unroll
    for (int j = 0; j < 4; j++) { int c = t + j * 1024; if (c < C) sp += e[j] * invt; }
    red[t] = sp; __syncthreads();
    for (int o = 512; o; o >>= 1) { if (t < o) red[t] += red[t + o]; __syncthreads(); }
    float mean = red[0] / C; __syncthreads();
    float ss = 0.f;
#pragma unroll
    for (int j = 0; j < 4; j++) {
        int c = t + j * 1024;
        if (c < C) { float dd = e[j] * invt - mean; ss += dd * dd; }
    }
    red[t] = ss; __syncthreads();
    for (int o = 512; o; o >>= 1) { if (t < o) red[t] += red[t + o]; __syncthreads(); }
    if (t == 0) {
        float stdv = sqrtf(red[0] / (C - 1));
        stdv = fminf(fmaxf(stdv, 1e-9f), 1e9f);
        out[0] = 64.f * stdv;
    }
}

// ---------------- launch ----------------
extern "C" void kernel_launch(void* const* d_in, const int* in_sizes, int n_in,
                              void* d_out, int out_size) {
    const float* seg = (const float*)d_in[0];
    const float* Wq  = (const float*)d_in[1];
    const float* bq  = (const float*)d_in[2];
    const float* Wk  = (const float*)d_in[3];
    const float* bk  = (const float*)d_in[4];
    const float* Wv  = (const float*)d_in[5];
    const float* bv  = (const float*)d_in[6];
    const float* Wc  = (const float*)d_in[7];
    const float* bc  = (const float*)d_in[8];
    const float* lna = (const float*)d_in[9];
    const float* lnb = (const float*)d_in[10];

    float* out  = (float*)d_out;
    float* vid  = out;                        // [B,C]
    float* idc  = out + B * C;                // [B,C]
    float* sco  = out + 2 * B * C;            // [B,S,H]
    float* attw = sco + B * S * H;            // [B,S,H]
    float* cl   = attw + B * S * H;           // [1]

    cudaFuncSetAttribute(gemm_mma, cudaFuncAttributeMaxDynamicSharedMemorySize, GEMM_SMEM);

    int n4 = BSZ * DM / 4;
    conv_seg<<<(n4 + 255) / 256, 256>>>((const float4*)seg, n4);
    fuse_wr<<<3072 + (C * 32 + 255) / 256, 256>>>(Wq, bq, Wk, bk, Wv, bv, Wc);
    convfin_k<<<1, 1024>>>(bc, cl);
    dim3 gg(NQ / 128, BSZ / 128);             // (6, 150) = 900 CTAs; 4th launch -> profiled
    gemm_mma<<<gg, 128, GEMM_SMEM>>>();
    attn_k<<<B, 512>>>(sco, attw);
    logits_gemm2<<<dim3((C + 63) / 64, 2), 256>>>(Wc, bc);
    ln_k<<<B * H, 512>>>(lna, lnb);
    final_k<<<(B * C + 255) / 256, 256>>>(vid, idc);
}

// round 13
// speedup vs baseline: 1.1744x; 1.1744x over previous
#include <cuda_runtime.h>
#include <cuda_fp16.h>
#include <math.h>
#include <stdint.h>

#define B 64
#define S 300
#define DM 1024
#define P 128
#define H 4
#define C 3862
#define BSZ (B*S)        /* 19200 */
#define NQ 768           /* 128 key + 128 val + 4*128 q */

// ---------------- scratch (static device globals; no allocation) ----------------
__device__ __align__(16) __half g_Ahi[(size_t)BSZ * DM];
__device__ __align__(16) __half g_Alo[(size_t)BSZ * DM];
__device__ __align__(16) __half g_Whi[NQ * DM];
__device__ __align__(16) __half g_Wlo[NQ * DM];
__device__ float g_bf[NQ];                 // fused bias
__device__ float g_qkv[(size_t)BSZ * NQ];  // [19200,768] fp32
__device__ float g_score[B * H * S];
__device__ float g_ws[B * H * P];
__device__ float g_logits[B * H * C];
__device__ float g_rowsum[C];

// ================= helpers =================
__device__ __forceinline__ uint32_t smem_u32(const void* p) {
    uint32_t a;
    asm("{ .reg .u64 t; cvta.to.shared.u64 t, %1; cvt.u32.u64 %0, t; }" : "=r"(a) : "l"(p));
    return a;
}
__device__ __forceinline__ void cp16(uint32_t s, const void* gp) {
    asm volatile("cp.async.cg.shared.global [%0], [%1], 16;" :: "r"(s), "l"(gp) : "memory");
}
__device__ __forceinline__ void ldsm4(uint32_t* r, uint32_t addr) {
    asm volatile("ldmatrix.sync.aligned.m8n8.x4.shared.b16 {%0,%1,%2,%3}, [%4];"
                 : "=r"(r[0]), "=r"(r[1]), "=r"(r[2]), "=r"(r[3]) : "r"(addr));
}
__device__ __forceinline__ void mma16816(float* c, const uint32_t* a, const uint32_t* b) {
    asm volatile("mma.sync.aligned.m16n8k16.row.col.f32.f16.f16.f32 "
                 "{%0,%1,%2,%3}, {%4,%5,%6,%7}, {%8,%9}, {%0,%1,%2,%3};"
                 : "+f"(c[0]), "+f"(c[1]), "+f"(c[2]), "+f"(c[3])
                 : "r"(a[0]), "r"(a[1]), "r"(a[2]), "r"(a[3]), "r"(b[0]), "r"(b[1]));
}

// ---------------- K0a: convert seg_features to split fp16 ----------------
__global__ void conv_seg(const float4* __restrict__ in, int n4) {
    int i = blockIdx.x * blockDim.x + threadIdx.x;
    if (i >= n4) return;
    float4 v = in[i];
    __half h0 = __float2half(v.x), h1 = __float2half(v.y);
    __half h2 = __float2half(v.z), h3 = __float2half(v.w);
    __half l0 = __float2half(v.x - __half2float(h0));
    __half l1 = __float2half(v.y - __half2float(h1));
    __half l2 = __float2half(v.z - __half2float(h2));
    __half l3 = __float2half(v.w - __half2float(h3));
    uint2 hw, lw;
    hw.x = (uint32_t)__half_as_ushort(h0) | ((uint32_t)__half_as_ushort(h1) << 16);
    hw.y = (uint32_t)__half_as_ushort(h2) | ((uint32_t)__half_as_ushort(h3) << 16);
    lw.x = (uint32_t)__half_as_ushort(l0) | ((uint32_t)__half_as_ushort(l1) << 16);
    lw.y = (uint32_t)__half_as_ushort(l2) | ((uint32_t)__half_as_ushort(l3) << 16);
    ((uint2*)g_Ahi)[i] = hw;
    ((uint2*)g_Alo)[i] = lw;
}

// ---------------- K0b: fuse+convert weights (blocks 0..3071) + Wc rowsums (blocks 3072+) ----------------
__global__ void fuse_wr(const float* __restrict__ Wq, const float* __restrict__ bq,
                        const float* __restrict__ Wk, const float* __restrict__ bk,
                        const float* __restrict__ Wv, const float* __restrict__ bv,
                        const float* __restrict__ Wc) {
    int blk = blockIdx.x;
    if (blk < 3072) {
        int idx = blk * 256 + threadIdx.x;
        if (idx < NQ * DM) {
            int n = idx >> 10, k = idx & 1023;
            float v;
            if (n < 128)      v = Wk[n * DM + k];
            else if (n < 256) v = Wv[(n - 128) * DM + k];
            else              v = Wq[(n - 256) * DM + k];
            __half h = __float2half(v);
            g_Whi[idx] = h;
            g_Wlo[idx] = __float2half(v - __half2float(h));
        }
        if (idx < NQ) {
            float v;
            if (idx < 128)      v = bk[idx];
            else if (idx < 256) v = bv[idx - 128];
            else                v = bq[idx - 256];
            g_bf[idx] = v;
        }
    } else {
        int w = ((blk - 3072) * 256 + threadIdx.x) >> 5;
        int lane = threadIdx.x & 31;
        if (w >= C) return;
        float4 v = *(const float4*)(Wc + (size_t)w * P + lane * 4);
        float s_ = v.x + v.y + v.z + v.w;
#pragma unroll
        for (int o = 16; o; o >>= 1) s_ += __shfl_xor_sync(0xffffffffu, s_, o);
        if (lane == 0) g_rowsum[w] = s_;
    }
}

// ---------------- K1: HMMA 3-term fp16 GEMM (R11 config, measured best) ----------------
#define STG_A_LO  6144u
#define STG_B_HI 12288u
#define STG_B_LO 18432u
#define STG_BYTES 24576u
#define GEMM_SMEM (4u * STG_BYTES)

__device__ __forceinline__ void load_stage(uint32_t sstage, int bm, int bn, int k0, int tid) {
#pragma unroll
    for (int i = 0; i < 8; i++) {
        int id = tid + i * 128;
        int sel = id >> 8;
        int j = id & 255;
        int row = j >> 1, kc = j & 1;
        uint32_t toff = (sel == 0) ? 0u : (sel == 1) ? STG_A_LO : (sel == 2) ? STG_B_HI : STG_B_LO;
        const __half* g = (sel == 0) ? g_Ahi : (sel == 1) ? g_Alo : (sel == 2) ? g_Whi : g_Wlo;
        int grow = (sel < 2) ? (bm + row) : (bn + row);
        cp16(sstage + toff + (uint32_t)(row * 48 + kc * 16),
             g + (size_t)grow * DM + k0 + kc * 8);
    }
    asm volatile("cp.async.commit_group;" ::: "memory");
}

__global__ __launch_bounds__(128, 2) void gemm_mma() {
    extern __shared__ char sm_[];
    uint32_t sbase = smem_u32(sm_);
    const int tid = threadIdx.x;
    const int wid = tid >> 5, lane = tid & 31;
    const int bm = blockIdx.y * 128, bn = blockIdx.x * 128;
    const int wm = (wid >> 1) * 64;
    const int wn = (wid & 1) * 64;
    const int g = lane >> 2, t = lane & 3;

    const uint32_t a_row = (uint32_t)(wm + (lane & 7) + ((lane >> 3) & 1) * 8);
    const uint32_t a_col = (uint32_t)((lane >> 4) * 16);
    const uint32_t b_row = (uint32_t)(wn + (lane & 7) + ((lane >> 4) & 1) * 8);
    const uint32_t b_col = (uint32_t)(((lane >> 3) & 1) * 16);

    float acc[4][8][4];
#pragma unroll
    for (int a = 0; a < 4; a++)
#pragma unroll
        for (int b = 0; b < 8; b++)
#pragma unroll
            for (int c = 0; c < 4; c++) acc[a][b][c] = 0.f;

    load_stage(sbase,                 bm, bn,  0, tid);
    load_stage(sbase + STG_BYTES,     bm, bn, 16, tid);
    load_stage(sbase + 2 * STG_BYTES, bm, bn, 32, tid);

    for (int kt = 0; kt < 64; kt++) {
        asm volatile("cp.async.wait_group 2;" ::: "memory");
        __syncthreads();
        if (kt + 3 < 64)
            load_stage(sbase + (uint32_t)((kt + 3) & 3) * STG_BYTES, bm, bn, (kt + 3) * 16, tid);
        else
            asm volatile("cp.async.commit_group;" ::: "memory");

        uint32_t st = sbase + (uint32_t)(kt & 3) * STG_BYTES;
        uint32_t ah[4][4], al[4][4];
#pragma unroll
        for (int mt = 0; mt < 4; mt++) {
            uint32_t ad = st + (a_row + (uint32_t)(mt * 16)) * 48u + a_col;
            ldsm4(ah[mt], ad);
            ldsm4(al[mt], ad + STG_A_LO);
        }
        uint32_t bh[2][4], bl[2][4];
        {
            uint32_t bd = st + STG_B_HI + b_row * 48u + b_col;
            ldsm4(bh[0], bd);
            ldsm4(bl[0], bd + (STG_B_LO - STG_B_HI));
        }
#pragma unroll
        for (int p = 0; p < 4; p++) {
            int cur = p & 1;
            if (p < 3) {
                uint32_t bd = st + STG_B_HI + (b_row + (uint32_t)((p + 1) * 16)) * 48u + b_col;
                ldsm4(bh[cur ^ 1], bd);
                ldsm4(bl[cur ^ 1], bd + (STG_B_LO - STG_B_HI));
            }
#pragma unroll
            for (int term = 0; term < 3; term++) {
#pragma unroll
                for (int sub = 0; sub < 2; sub++) {
#pragma unroll
                    for (int mt = 0; mt < 4; mt++) {
                        const uint32_t* af = (term == 2) ? al[mt] : ah[mt];
                        const uint32_t* bf = (term == 1) ? &bl[cur][2 * sub] : &bh[cur][2 * sub];
                        mma16816(acc[mt][p * 2 + sub], af, bf);
                    }
                }
            }
        }
    }

#pragma unroll
    for (int mt = 0; mt < 4; mt++) {
        int r0 = bm + wm + mt * 16 + g;
#pragma unroll
        for (int nt = 0; nt < 8; nt++) {
            int col = bn + wn + nt * 8 + 2 * t;
            float2 bv = *(const float2*)(g_bf + col);
            float2 v0 = { acc[mt][nt][0] + bv.x, acc[mt][nt][1] + bv.y };
            *(float2*)(g_qkv + (size_t)r0 * NQ + col) = v0;
            float2 v1 = { acc[mt][nt][2] + bv.x, acc[mt][nt][3] + bv.y };
            *(float2*)(g_qkv + (size_t)(r0 + 8) * NQ + col) = v1;
        }
    }
}

// ---------------- K2: scores[b,h,s] = dot(q,k)*scale (R11 version) ----------------
__global__ void scores_k(float* __restrict__ sco_out) {
    int bs = blockIdx.x;
    int b = bs / S, s = bs % S;
    int h = threadIdx.x >> 5, lane = threadIdx.x & 31;
    const float* rowp = g_qkv + (size_t)bs * NQ;
    float4 q = *(const float4*)(rowp + 256 + h * 128 + lane * 4);
    float4 k = *(const float4*)(rowp + lane * 4);
    float d = q.x * k.x + q.y * k.y + q.z * k.z + q.w * k.w;
#pragma unroll
    for (int o = 16; o; o >>= 1) d += __shfl_xor_sync(0xffffffffu, d, o);
    if (lane == 0) {
        float v = d * 0.08838834764831845f;
        g_score[(b * H + h) * S + s] = v;
        sco_out[(size_t)bs * H + h] = v;
    }
}

// ---------------- K3: fused softmax + ws per (b,h), 256 threads ----------------
__global__ __launch_bounds__(256) void softmax_ws_k(float* __restrict__ attw_out) {
    int row = blockIdx.x;                 // b*H + h
    int b = row >> 2, h = row & 3;
    __shared__ float sp[304];
    __shared__ float red[256];
    __shared__ float part[128];
    int t = threadIdx.x;
    float x0 = g_score[row * S + t % S];  // t<256<300 always valid; use direct
    x0 = g_score[row * S + t];            // t in [0,256) < 300
    float x1 = (t + 256 < S) ? g_score[row * S + t + 256] : -1e30f;
    red[t] = fmaxf(x0, x1); __syncthreads();
    for (int o = 128; o; o >>= 1) { if (t < o) red[t] = fmaxf(red[t], red[t + o]); __syncthreads(); }
    float mx = red[0]; __syncthreads();
    float e0 = expf(x0 - mx);
    float e1 = (t + 256 < S) ? expf(x1 - mx) : 0.f;
    red[t] = e0 + e1; __syncthreads();
    for (int o = 128; o; o >>= 1) { if (t < o) red[t] += red[t + o]; __syncthreads(); }
    float inv = 1.f / red[0];
    {
        float pr = e0 * inv;
        sp[t] = pr;
        attw_out[(size_t)(b * S + t) * H + h] = pr;
    }
    if (t + 256 < S) {
        float pr = e1 * inv;
        sp[t + 256] = pr;
        attw_out[(size_t)(b * S + t + 256) * H + h] = pr;
    }
    __syncthreads();
    // ws phase: 2 halves of S, 128 P-lanes each
    int p = t & 127, half = t >> 7;
    int base = half * 150;
    const float* vp = g_qkv + (size_t)b * S * NQ + 128 + p;
    float a0 = 0.f, a1 = 0.f;
#pragma unroll 2
    for (int s = base; s < base + 150; s += 2) {
        a0 = fmaf(sp[s],     vp[(size_t)s * NQ], a0);
        a1 = fmaf(sp[s + 1], vp[(size_t)(s + 1) * NQ], a1);
    }
    float sum = a0 + a1;
    if (half == 1) part[p] = sum;
    __syncthreads();
    if (half == 0) g_ws[row * P + p] = fmaxf(sum + part[p], 0.f);
}

// ---------------- K5a: logits = relu(ws) @ Wc^T + bc  (register-tiled SIMT GEMM) ----------------
#define LG_CW 68
#define LG_RW 136
__global__ __launch_bounds__(256) void logits_gemm2(const float* __restrict__ Wc,
                                                    const float* __restrict__ bc) {
    __shared__ float sWcT[128][LG_CW];
    __shared__ float sWsT[128][LG_RW];
    int tid = threadIdx.x;
    int c_base = blockIdx.x * 64, r_base = blockIdx.y * 128;

#pragma unroll
    for (int u = 0; u < 8; u++) {
        int idx = tid + u * 256;
        int c = idx >> 5, kq = idx & 31;
        float4 v = make_float4(0.f, 0.f, 0.f, 0.f);
        if (c_base + c < C) v = *(const float4*)(Wc + (size_t)(c_base + c) * P + kq * 4);
        sWcT[kq * 4 + 0][c] = v.x; sWcT[kq * 4 + 1][c] = v.y;
        sWcT[kq * 4 + 2][c] = v.z; sWcT[kq * 4 + 3][c] = v.w;
    }
#pragma unroll
    for (int u = 0; u < 16; u++) {
        int idx = tid + u * 256;
        int r = idx >> 5, kq = idx & 31;
        float4 v = *(const float4*)(g_ws + (size_t)(r_base + r) * P + kq * 4);
        sWsT[kq * 4 + 0][r] = v.x; sWsT[kq * 4 + 1][r] = v.y;
        sWsT[kq * 4 + 2][r] = v.z; sWsT[kq * 4 + 3][r] = v.w;
    }
    __syncthreads();

    int cg = tid & 15, rg = tid >> 4;
    float acc[4][8];
#pragma unroll
    for (int i = 0; i < 4; i++)
#pragma unroll
        for (int j = 0; j < 8; j++) acc[i][j] = 0.f;

    for (int k = 0; k < 128; k++) {
        float4 a4 = *(const float4*)&sWcT[k][cg * 4];
        float4 b0 = *(const float4*)&sWsT[k][rg * 8];
        float4 b1 = *(const float4*)&sWsT[k][rg * 8 + 4];
        float a[4] = { a4.x, a4.y, a4.z, a4.w };
        float bb[8] = { b0.x, b0.y, b0.z, b0.w, b1.x, b1.y, b1.z, b1.w };
#pragma unroll
        for (int i = 0; i < 4; i++)
#pragma unroll
            for (int j = 0; j < 8; j++)
                acc[i][j] = fmaf(a[i], bb[j], acc[i][j]);
    }

#pragma unroll
    for (int i = 0; i < 4; i++) {
        int c = c_base + cg * 4 + i;
        if (c >= C) continue;
        float bcv = bc[c];
#pragma unroll
        for (int j = 0; j < 8; j++) {
            int r = r_base + rg * 8 + j;
            g_logits[(size_t)r * C + c] = acc[i][j] + bcv;
        }
    }
}

// ---------------- K5b: LayerNorm (torch variant) in-place on g_logits ----------------
__global__ __launch_bounds__(512) void ln_k(const float* __restrict__ lna,
                                            const float* __restrict__ lnb) {
    int row = blockIdx.x;
    __shared__ float slog[C];
    __shared__ float red[512];
    int t = threadIdx.x;
    for (int c = t; c < C; c += 512) slog[c] = g_logits[(size_t)row * C + c];
    __syncthreads();
    float ps = 0.f;
    for (int c = t; c < C; c += 512) ps += slog[c];
    red[t] = ps; __syncthreads();
    for (int o = 256; o; o >>= 1) { if (t < o) red[t] += red[t + o]; __syncthreads(); }
    float mean = red[0] / C; __syncthreads();
    float ps2 = 0.f;
    for (int c = t; c < C; c += 512) { float dd = slog[c] - mean; ps2 += dd * dd; }
    red[t] = ps2; __syncthreads();
    for (int o = 256; o; o >>= 1) { if (t < o) red[t] += red[t + o]; __syncthreads(); }
    float stdv = sqrtf(red[0] / (C - 1));
    float inv = 1.f / (stdv + 1e-6f);
    for (int c = t; c < C; c += 512)
        g_logits[(size_t)row * C + c] = lna[c] * (slog[c] - mean) * inv + lnb[c];
}

// ---------------- K6: per (b,c) max/argmax over H, sigmoid ----------------
__global__ void final_k(float* __restrict__ vid, float* __restrict__ idc) {
    int idx = blockIdx.x * blockDim.x + threadIdx.x;
    if (idx >= B * C) return;
    int b = idx / C, c = idx % C;
    const float* lp = g_logits + (size_t)b * H * C + c;
    float best = lp[0]; int arg = 0;
#pragma unroll
    for (int h = 1; h < H; h++) {
        float v = lp[(size_t)h * C];
        if (v > best) { best = v; arg = h; }
    }
    vid[idx] = 1.f / (1.f + expf(-best));
    idc[idx] = (float)arg;
}

// ---------------- K7: conv regularizer finisher (1 block, cheap) ----------------
__global__ __launch_bounds__(1024) void convfin_k(const float* __restrict__ bc,
                                                  float* __restrict__ out) {
    __shared__ float red[1024];
    int t = threadIdx.x;
    float v[4]; float lm = -1e30f;
#pragma unroll
    for (int j = 0; j < 4; j++) {
        int c = t + j * 1024;
        if (c < C) { v[j] = g_rowsum[c] + bc[c]; lm = fmaxf(lm, v[j]); }
        else v[j] = -1e30f;
    }
    red[t] = lm; __syncthreads();
    for (int o = 512; o; o >>= 1) { if (t < o) red[t] = fmaxf(red[t], red[t + o]); __syncthreads(); }
    float mx = red[0]; __syncthreads();
    float e[4]; float psum = 0.f;
#pragma unroll
    for (int j = 0; j < 4; j++) {
        int c = t + j * 1024;
        e[j] = (c < C) ? expf(v[j] - mx) : 0.f;
        psum += e[j];
    }
    red[t] = psum; __syncthreads();
    for (int o = 512; o; o >>= 1) { if (t < o) red[t] += red[t + o]; __syncthreads(); }
    float invt = 1.f / red[0]; __syncthreads();
    float sp = 0.f;
#pragma unroll
    for (int j = 0; j < 4; j++) { int c = t + j * 1024; if (c < C) sp += e[j] * invt; }
    red[t] = sp; __syncthreads();
    for (int o = 512; o; o >>= 1) { if (t < o) red[t] += red[t + o]; __syncthreads(); }
    float mean = red[0] / C; __syncthreads();
    float ss = 0.f;
#pragma unroll
    for (int j = 0; j < 4; j++) {
        int c = t + j * 1024;
        if (c < C) { float dd = e[j] * invt - mean; ss += dd * dd; }
    }
    red[t] = ss; __syncthreads();
    for (int o = 512; o; o >>= 1) { if (t < o) red[t] += red[t + o]; __syncthreads(); }
    if (t == 0) {
        float stdv = sqrtf(red[0] / (C - 1));
        stdv = fminf(fmaxf(stdv, 1e-9f), 1e9f);
        out[0] = 64.f * stdv;
    }
}

// ---------------- launch ----------------
extern "C" void kernel_launch(void* const* d_in, const int* in_sizes, int n_in,
                              void* d_out, int out_size) {
    const float* seg = (const float*)d_in[0];
    const float* Wq  = (const float*)d_in[1];
    const float* bq  = (const float*)d_in[2];
    const float* Wk  = (const float*)d_in[3];
    const float* bk  = (const float*)d_in[4];
    const float* Wv  = (const float*)d_in[5];
    const float* bv  = (const float*)d_in[6];
    const float* Wc  = (const float*)d_in[7];
    const float* bc  = (const float*)d_in[8];
    const float* lna = (const float*)d_in[9];
    const float* lnb = (const float*)d_in[10];

    float* out  = (float*)d_out;
    float* vid  = out;                        // [B,C]
    float* idc  = out + B * C;                // [B,C]
    float* sco  = out + 2 * B * C;            // [B,S,H]
    float* attw = sco + B * S * H;            // [B,S,H]
    float* cl   = attw + B * S * H;           // [1]

    cudaFuncSetAttribute(gemm_mma, cudaFuncAttributeMaxDynamicSharedMemorySize, GEMM_SMEM);

    int n4 = BSZ * DM / 4;
    conv_seg<<<(n4 + 255) / 256, 256>>>((const float4*)seg, n4);
    fuse_wr<<<3072 + (C * 32 + 255) / 256, 256>>>(Wq, bq, Wk, bk, Wv, bv, Wc);
    convfin_k<<<1, 1024>>>(bc, cl);
    dim3 gg(NQ / 128, BSZ / 128);             // (6, 150) = 900 CTAs; 4th launch -> profiled
    gemm_mma<<<gg, 128, GEMM_SMEM>>>();
    scores_k<<<BSZ, 128>>>(sco);
    softmax_ws_k<<<B * H, 256>>>(attw);
    logits_gemm2<<<dim3((C + 63) / 64, 2), 256>>>(Wc, bc);
    ln_k<<<B * H, 512>>>(lna, lnb);
    final_k<<<(B * C + 255) / 256, 256>>>(vid, idc);
}

// round 14
// speedup vs baseline: 1.1819x; 1.0063x over previous
#include <cuda_runtime.h>
#include <cuda_fp16.h>
#include <math.h>
#include <stdint.h>

#define B 64
#define S 300
#define DM 1024
#define P 128
#define H 4
#define C 3862
#define BSZ (B*S)        /* 19200 */
#define NQ 768           /* 128 key + 128 val + 4*128 q */
#define N4 (BSZ * DM / 4)          /* 4,915,200 float4 -> 19200 blocks */
#define PREP_CONV_BLKS 19200
#define PREP_FUSE_BLKS 3072
#define PREP_ROWS_BLKS ((C * 32 + 255) / 256)

// ---------------- scratch (static device globals; no allocation) ----------------
__device__ __align__(16) __half g_Ahi[(size_t)BSZ * DM];
__device__ __align__(16) __half g_Alo[(size_t)BSZ * DM];
__device__ __align__(16) __half g_Whi[NQ * DM];
__device__ __align__(16) __half g_Wlo[NQ * DM];
__device__ float g_bf[NQ];
__device__ float g_qkv[(size_t)BSZ * NQ];
__device__ float g_score[B * H * S];
__device__ float g_ws[B * H * P];
__device__ float g_logits[B * H * C];
__device__ float g_rowsum[C];

// ================= helpers =================
__device__ __forceinline__ uint32_t smem_u32(const void* p) {
    uint32_t a;
    asm("{ .reg .u64 t; cvta.to.shared.u64 t, %1; cvt.u32.u64 %0, t; }" : "=r"(a) : "l"(p));
    return a;
}
__device__ __forceinline__ void cp16(uint32_t s, const void* gp) {
    asm volatile("cp.async.cg.shared.global [%0], [%1], 16;" :: "r"(s), "l"(gp) : "memory");
}
__device__ __forceinline__ void ldsm4(uint32_t* r, uint32_t addr) {
    asm volatile("ldmatrix.sync.aligned.m8n8.x4.shared.b16 {%0,%1,%2,%3}, [%4];"
                 : "=r"(r[0]), "=r"(r[1]), "=r"(r[2]), "=r"(r[3]) : "r"(addr));
}
__device__ __forceinline__ void mma16816(float* c, const uint32_t* a, const uint32_t* b) {
    asm volatile("mma.sync.aligned.m16n8k16.row.col.f32.f16.f16.f32 "
                 "{%0,%1,%2,%3}, {%4,%5,%6,%7}, {%8,%9}, {%0,%1,%2,%3};"
                 : "+f"(c[0]), "+f"(c[1]), "+f"(c[2]), "+f"(c[3])
                 : "r"(a[0]), "r"(a[1]), "r"(a[2]), "r"(a[3]), "r"(b[0]), "r"(b[1]));
}

// ---------------- K0: unified prep (A conversion || weight fuse+convert || Wc rowsums) ----------------
__global__ void prep_k(const float4* __restrict__ seg4,
                       const float* __restrict__ Wq, const float* __restrict__ bq,
                       const float* __restrict__ Wk, const float* __restrict__ bk,
                       const float* __restrict__ Wv, const float* __restrict__ bv,
                       const float* __restrict__ Wc) {
    int blk = blockIdx.x;
    if (blk < PREP_CONV_BLKS) {
        int i = blk * 256 + threadIdx.x;
        if (i >= N4) return;
        float4 v = seg4[i];
        __half h0 = __float2half(v.x), h1 = __float2half(v.y);
        __half h2 = __float2half(v.z), h3 = __float2half(v.w);
        __half l0 = __float2half(v.x - __half2float(h0));
        __half l1 = __float2half(v.y - __half2float(h1));
        __half l2 = __float2half(v.z - __half2float(h2));
        __half l3 = __float2half(v.w - __half2float(h3));
        uint2 hw, lw;
        hw.x = (uint32_t)__half_as_ushort(h0) | ((uint32_t)__half_as_ushort(h1) << 16);
        hw.y = (uint32_t)__half_as_ushort(h2) | ((uint32_t)__half_as_ushort(h3) << 16);
        lw.x = (uint32_t)__half_as_ushort(l0) | ((uint32_t)__half_as_ushort(l1) << 16);
        lw.y = (uint32_t)__half_as_ushort(l2) | ((uint32_t)__half_as_ushort(l3) << 16);
        ((uint2*)g_Ahi)[i] = hw;
        ((uint2*)g_Alo)[i] = lw;
    } else if (blk < PREP_CONV_BLKS + PREP_FUSE_BLKS) {
        int idx = (blk - PREP_CONV_BLKS) * 256 + threadIdx.x;
        if (idx < NQ * DM) {
            int n = idx >> 10, k = idx & 1023;
            float v;
            if (n < 128)      v = Wk[n * DM + k];
            else if (n < 256) v = Wv[(n - 128) * DM + k];
            else              v = Wq[(n - 256) * DM + k];
            __half h = __float2half(v);
            g_Whi[idx] = h;
            g_Wlo[idx] = __float2half(v - __half2float(h));
        }
        if (idx < NQ) {
            float v;
            if (idx < 128)      v = bk[idx];
            else if (idx < 256) v = bv[idx - 128];
            else                v = bq[idx - 256];
            g_bf[idx] = v;
        }
    } else {
        int w = ((blk - PREP_CONV_BLKS - PREP_FUSE_BLKS) * 256 + threadIdx.x) >> 5;
        int lane = threadIdx.x & 31;
        if (w >= C) return;
        float4 v = *(const float4*)(Wc + (size_t)w * P + lane * 4);
        float s_ = v.x + v.y + v.z + v.w;
#pragma unroll
        for (int o = 16; o; o >>= 1) s_ += __shfl_xor_sync(0xffffffffu, s_, o);
        if (lane == 0) g_rowsum[w] = s_;
    }
}

// ---------------- K1: HMMA 3-term fp16 GEMM (R11 config, measured best) ----------------
#define STG_A_LO  6144u
#define STG_B_HI 12288u
#define STG_B_LO 18432u
#define STG_BYTES 24576u
#define GEMM_SMEM (4u * STG_BYTES)

__device__ __forceinline__ void load_stage(uint32_t sstage, int bm, int bn, int k0, int tid) {
#pragma unroll
    for (int i = 0; i < 8; i++) {
        int id = tid + i * 128;
        int sel = id >> 8;
        int j = id & 255;
        int row = j >> 1, kc = j & 1;
        uint32_t toff = (sel == 0) ? 0u : (sel == 1) ? STG_A_LO : (sel == 2) ? STG_B_HI : STG_B_LO;
        const __half* g = (sel == 0) ? g_Ahi : (sel == 1) ? g_Alo : (sel == 2) ? g_Whi : g_Wlo;
        int grow = (sel < 2) ? (bm + row) : (bn + row);
        cp16(sstage + toff + (uint32_t)(row * 48 + kc * 16),
             g + (size_t)grow * DM + k0 + kc * 8);
    }
    asm volatile("cp.async.commit_group;" ::: "memory");
}

__global__ __launch_bounds__(128, 2) void gemm_mma() {
    extern __shared__ char sm_[];
    uint32_t sbase = smem_u32(sm_);
    const int tid = threadIdx.x;
    const int wid = tid >> 5, lane = tid & 31;
    const int bm = blockIdx.y * 128, bn = blockIdx.x * 128;
    const int wm = (wid >> 1) * 64;
    const int wn = (wid & 1) * 64;
    const int g = lane >> 2, t = lane & 3;

    const uint32_t a_row = (uint32_t)(wm + (lane & 7) + ((lane >> 3) & 1) * 8);
    const uint32_t a_col = (uint32_t)((lane >> 4) * 16);
    const uint32_t b_row = (uint32_t)(wn + (lane & 7) + ((lane >> 4) & 1) * 8);
    const uint32_t b_col = (uint32_t)(((lane >> 3) & 1) * 16);

    float acc[4][8][4];
#pragma unroll
    for (int a = 0; a < 4; a++)
#pragma unroll
        for (int b = 0; b < 8; b++)
#pragma unroll
            for (int c = 0; c < 4; c++) acc[a][b][c] = 0.f;

    load_stage(sbase,                 bm, bn,  0, tid);
    load_stage(sbase + STG_BYTES,     bm, bn, 16, tid);
    load_stage(sbase + 2 * STG_BYTES, bm, bn, 32, tid);

    for (int kt = 0; kt < 64; kt++) {
        asm volatile("cp.async.wait_group 2;" ::: "memory");
        __syncthreads();
        if (kt + 3 < 64)
            load_stage(sbase + (uint32_t)((kt + 3) & 3) * STG_BYTES, bm, bn, (kt + 3) * 16, tid);
        else
            asm volatile("cp.async.commit_group;" ::: "memory");

        uint32_t st = sbase + (uint32_t)(kt & 3) * STG_BYTES;
        uint32_t ah[4][4], al[4][4];
#pragma unroll
        for (int mt = 0; mt < 4; mt++) {
            uint32_t ad = st + (a_row + (uint32_t)(mt * 16)) * 48u + a_col;
            ldsm4(ah[mt], ad);
            ldsm4(al[mt], ad + STG_A_LO);
        }
        uint32_t bh[2][4], bl[2][4];
        {
            uint32_t bd = st + STG_B_HI + b_row * 48u + b_col;
            ldsm4(bh[0], bd);
            ldsm4(bl[0], bd + (STG_B_LO - STG_B_HI));
        }
#pragma unroll
        for (int p = 0; p < 4; p++) {
            int cur = p & 1;
            if (p < 3) {
                uint32_t bd = st + STG_B_HI + (b_row + (uint32_t)((p + 1) * 16)) * 48u + b_col;
                ldsm4(bh[cur ^ 1], bd);
                ldsm4(bl[cur ^ 1], bd + (STG_B_LO - STG_B_HI));
            }
#pragma unroll
            for (int term = 0; term < 3; term++) {
#pragma unroll
                for (int sub = 0; sub < 2; sub++) {
#pragma unroll
                    for (int mt = 0; mt < 4; mt++) {
                        const uint32_t* af = (term == 2) ? al[mt] : ah[mt];
                        const uint32_t* bf = (term == 1) ? &bl[cur][2 * sub] : &bh[cur][2 * sub];
                        mma16816(acc[mt][p * 2 + sub], af, bf);
                    }
                }
            }
        }
    }

#pragma unroll
    for (int mt = 0; mt < 4; mt++) {
        int r0 = bm + wm + mt * 16 + g;
#pragma unroll
        for (int nt = 0; nt < 8; nt++) {
            int col = bn + wn + nt * 8 + 2 * t;
            float2 bv = *(const float2*)(g_bf + col);
            float2 v0 = { acc[mt][nt][0] + bv.x, acc[mt][nt][1] + bv.y };
            *(float2*)(g_qkv + (size_t)r0 * NQ + col) = v0;
            float2 v1 = { acc[mt][nt][2] + bv.x, acc[mt][nt][3] + bv.y };
            *(float2*)(g_qkv + (size_t)(r0 + 8) * NQ + col) = v1;
        }
    }
}

// ---------------- K2: scores[b,h,s] = dot(q,k)*scale (K staged in smem once per block) ----------------
__global__ void scores_k(float* __restrict__ sco_out) {
    int bs = blockIdx.x;
    int b = bs / S, s = bs % S;
    int tid = threadIdx.x;
    int h = tid >> 5, lane = tid & 31;
    __shared__ float sk[128];
    const float* rowp = g_qkv + (size_t)bs * NQ;
    sk[tid] = rowp[tid];
    __syncthreads();
    float4 q = *(const float4*)(rowp + 256 + h * 128 + lane * 4);
    float4 k = *(const float4*)(sk + lane * 4);
    float d = q.x * k.x + q.y * k.y + q.z * k.z + q.w * k.w;
#pragma unroll
    for (int o = 16; o; o >>= 1) d += __shfl_xor_sync(0xffffffffu, d, o);
    if (lane == 0) {
        float v = d * 0.08838834764831845f;
        g_score[(b * H + h) * S + s] = v;
        sco_out[(size_t)bs * H + h] = v;
    }
}

// ---------------- K3: fused softmax + ws per (b,h), 256 threads ----------------
__global__ __launch_bounds__(256) void softmax_ws_k(float* __restrict__ attw_out) {
    int row = blockIdx.x;
    int b = row >> 2, h = row & 3;
    __shared__ float sp[304];
    __shared__ float red[256];
    __shared__ float part[128];
    int t = threadIdx.x;
    float x0 = g_score[row * S + t];
    float x1 = (t + 256 < S) ? g_score[row * S + t + 256] : -1e30f;
    red[t] = fmaxf(x0, x1); __syncthreads();
    for (int o = 128; o; o >>= 1) { if (t < o) red[t] = fmaxf(red[t], red[t + o]); __syncthreads(); }
    float mx = red[0]; __syncthreads();
    float e0 = expf(x0 - mx);
    float e1 = (t + 256 < S) ? expf(x1 - mx) : 0.f;
    red[t] = e0 + e1; __syncthreads();
    for (int o = 128; o; o >>= 1) { if (t < o) red[t] += red[t + o]; __syncthreads(); }
    float inv = 1.f / red[0];
    {
        float pr = e0 * inv;
        sp[t] = pr;
        attw_out[(size_t)(b * S + t) * H + h] = pr;
    }
    if (t + 256 < S) {
        float pr = e1 * inv;
        sp[t + 256] = pr;
        attw_out[(size_t)(b * S + t + 256) * H + h] = pr;
    }
    __syncthreads();
    int p = t & 127, half = t >> 7;
    int base = half * 150;
    const float* vp = g_qkv + (size_t)b * S * NQ + 128 + p;
    float a0 = 0.f, a1 = 0.f;
#pragma unroll 2
    for (int s = base; s < base + 150; s += 2) {
        a0 = fmaf(sp[s],     vp[(size_t)s * NQ], a0);
        a1 = fmaf(sp[s + 1], vp[(size_t)(s + 1) * NQ], a1);
    }
    float sum = a0 + a1;
    if (half == 1) part[p] = sum;
    __syncthreads();
    if (half == 0) g_ws[row * P + p] = fmaxf(sum + part[p], 0.f);
}

// ---------------- K4: logits = relu(ws) @ Wc^T + bc ----------------
#define LG_CW 68
#define LG_RW 136
__global__ __launch_bounds__(256) void logits_gemm2(const float* __restrict__ Wc,
                                                    const float* __restrict__ bc) {
    __shared__ float sWcT[128][LG_CW];
    __shared__ float sWsT[128][LG_RW];
    int tid = threadIdx.x;
    int c_base = blockIdx.x * 64, r_base = blockIdx.y * 128;

#pragma unroll
    for (int u = 0; u < 8; u++) {
        int idx = tid + u * 256;
        int c = idx >> 5, kq = idx & 31;
        float4 v = make_float4(0.f, 0.f, 0.f, 0.f);
        if (c_base + c < C) v = *(const float4*)(Wc + (size_t)(c_base + c) * P + kq * 4);
        sWcT[kq * 4 + 0][c] = v.x; sWcT[kq * 4 + 1][c] = v.y;
        sWcT[kq * 4 + 2][c] = v.z; sWcT[kq * 4 + 3][c] = v.w;
    }
#pragma unroll
    for (int u = 0; u < 16; u++) {
        int idx = tid + u * 256;
        int r = idx >> 5, kq = idx & 31;
        float4 v = *(const float4*)(g_ws + (size_t)(r_base + r) * P + kq * 4);
        sWsT[kq * 4 + 0][r] = v.x; sWsT[kq * 4 + 1][r] = v.y;
        sWsT[kq * 4 + 2][r] = v.z; sWsT[kq * 4 + 3][r] = v.w;
    }
    __syncthreads();

    int cg = tid & 15, rg = tid >> 4;
    float acc[4][8];
#pragma unroll
    for (int i = 0; i < 4; i++)
#pragma unroll
        for (int j = 0; j < 8; j++) acc[i][j] = 0.f;

    for (int k = 0; k < 128; k++) {
        float4 a4 = *(const float4*)&sWcT[k][cg * 4];
        float4 b0 = *(const float4*)&sWsT[k][rg * 8];
        float4 b1 = *(const float4*)&sWsT[k][rg * 8 + 4];
        float a[4] = { a4.x, a4.y, a4.z, a4.w };
        float bb[8] = { b0.x, b0.y, b0.z, b0.w, b1.x, b1.y, b1.z, b1.w };
#pragma unroll
        for (int i = 0; i < 4; i++)
#pragma unroll
            for (int j = 0; j < 8; j++)
                acc[i][j] = fmaf(a[i], bb[j], acc[i][j]);
    }

#pragma unroll
    for (int i = 0; i < 4; i++) {
        int c = c_base + cg * 4 + i;
        if (c >= C) continue;
        float bcv = bc[c];
#pragma unroll
        for (int j = 0; j < 8; j++) {
            int r = r_base + rg * 8 + j;
            g_logits[(size_t)r * C + c] = acc[i][j] + bcv;
        }
    }
}

// ---------------- K5: LayerNorm in-place on g_logits ----------------
__global__ __launch_bounds__(512) void ln_k(const float* __restrict__ lna,
                                            const float* __restrict__ lnb) {
    int row = blockIdx.x;
    __shared__ float slog[C];
    __shared__ float red[512];
    int t = threadIdx.x;
    for (int c = t; c < C; c += 512) slog[c] = g_logits[(size_t)row * C + c];
    __syncthreads();
    float ps = 0.f;
    for (int c = t; c < C; c += 512) ps += slog[c];
    red[t] = ps; __syncthreads();
    for (int o = 256; o; o >>= 1) { if (t < o) red[t] += red[t + o]; __syncthreads(); }
    float mean = red[0] / C; __syncthreads();
    float ps2 = 0.f;
    for (int c = t; c < C; c += 512) { float dd = slog[c] - mean; ps2 += dd * dd; }
    red[t] = ps2; __syncthreads();
    for (int o = 256; o; o >>= 1) { if (t < o) red[t] += red[t + o]; __syncthreads(); }
    float stdv = sqrtf(red[0] / (C - 1));
    float inv = 1.f / (stdv + 1e-6f);
    for (int c = t; c < C; c += 512)
        g_logits[(size_t)row * C + c] = lna[c] * (slog[c] - mean) * inv + lnb[c];
}

// ---------------- K6: per (b,c) max/argmax over H, sigmoid ----------------
__global__ void final_k(float* __restrict__ vid, float* __restrict__ idc) {
    int idx = blockIdx.x * blockDim.x + threadIdx.x;
    if (idx >= B * C) return;
    int b = idx / C, c = idx % C;
    const float* lp = g_logits + (size_t)b * H * C + c;
    float best = lp[0]; int arg = 0;
#pragma unroll
    for (int h = 1; h < H; h++) {
        float v = lp[(size_t)h * C];
        if (v > best) { best = v; arg = h; }
    }
    vid[idx] = 1.f / (1.f + expf(-best));
    idc[idx] = (float)arg;
}

// ---------------- K7: conv regularizer finisher ----------------
__global__ __launch_bounds__(1024) void convfin_k(const float* __restrict__ bc,
                                                  float* __restrict__ out) {
    __shared__ float red[1024];
    int t = threadIdx.x;
    float v[4]; float lm = -1e30f;
#pragma unroll
    for (int j = 0; j < 4; j++) {
        int c = t + j * 1024;
        if (c < C) { v[j] = g_rowsum[c] + bc[c]; lm = fmaxf(lm, v[j]); }
        else v[j] = -1e30f;
    }
    red[t] = lm; __syncthreads();
    for (int o = 512; o; o >>= 1) { if (t < o) red[t] = fmaxf(red[t], red[t + o]); __syncthreads(); }
    float mx = red[0]; __syncthreads();
    float e[4]; float psum = 0.f;
#pragma unroll
    for (int j = 0; j < 4; j++) {
        int c = t + j * 1024;
        e[j] = (c < C) ? expf(v[j] - mx) : 0.f;
        psum += e[j];
    }
    red[t] = psum; __syncthreads();
    for (int o = 512; o; o >>= 1) { if (t < o) red[t] += red[t + o]; __syncthreads(); }
    float invt = 1.f / red[0]; __syncthreads();
    float sp = 0.f;
#pragma unroll
    for (int j = 0; j < 4; j++) { int c = t + j * 1024; if (c < C) sp += e[j] * invt; }
    red[t] = sp; __syncthreads();
    for (int o = 512; o; o >>= 1) { if (t < o) red[t] += red[t + o]; __syncthreads(); }
    float mean = red[0] / C; __syncthreads();
    float ss = 0.f;
#pragma unroll
    for (int j = 0; j < 4; j++) {
        int c = t + j * 1024;
        if (c < C) { float dd = e[j] * invt - mean; ss += dd * dd; }
    }
    red[t] = ss; __syncthreads();
    for (int o = 512; o; o >>= 1) { if (t < o) red[t] += red[t + o]; __syncthreads(); }
    if (t == 0) {
        float stdv = sqrtf(red[0] / (C - 1));
        stdv = fminf(fmaxf(stdv, 1e-9f), 1e9f);
        out[0] = 64.f * stdv;
    }
}

// ---------------- launch ----------------
extern "C" void kernel_launch(void* const* d_in, const int* in_sizes, int n_in,
                              void* d_out, int out_size) {
    const float* seg = (const float*)d_in[0];
    const float* Wq  = (const float*)d_in[1];
    const float* bq  = (const float*)d_in[2];
    const float* Wk  = (const float*)d_in[3];
    const float* bk  = (const float*)d_in[4];
    const float* Wv  = (const float*)d_in[5];
    const float* bv  = (const float*)d_in[6];
    const float* Wc  = (const float*)d_in[7];
    const float* bc  = (const float*)d_in[8];
    const float* lna = (const float*)d_in[9];
    const float* lnb = (const float*)d_in[10];

    float* out  = (float*)d_out;
    float* vid  = out;
    float* idc  = out + B * C;
    float* sco  = out + 2 * B * C;
    float* attw = sco + B * S * H;
    float* cl   = attw + B * S * H;

    cudaFuncSetAttribute(gemm_mma, cudaFuncAttributeMaxDynamicSharedMemorySize, GEMM_SMEM);

    prep_k<<<PREP_CONV_BLKS + PREP_FUSE_BLKS + PREP_ROWS_BLKS, 256>>>(
        (const float4*)seg, Wq, bq, Wk, bk, Wv, bv, Wc);
    convfin_k<<<1, 1024>>>(bc, cl);
    dim3 gg(NQ / 128, BSZ / 128);             // (6, 150) = 900 CTAs
    gemm_mma<<<gg, 128, GEMM_SMEM>>>();
    scores_k<<<BSZ, 128>>>(sco);              // 4th launch -> profiled
    softmax_ws_k<<<B * H, 256>>>(attw);
    logits_gemm2<<<dim3((C + 63) / 64, 2), 256>>>(Wc, bc);
    ln_k<<<B * H, 512>>>(lna, lnb);
    final_k<<<(B * C + 255) / 256, 256>>>(vid, idc);
}